// round 15
// baseline (speedup 1.0000x reference)
#include <cuda_runtime.h>
#include <cuda_fp16.h>
#include <cstdint>
#include <math.h>

// ---------------- problem constants ----------------
#define HIN 256
#define WIN 256
#define HOUT 128
#define WOUT 128
#define CIN 128
#define CO_OFF 1152      // G*2*K
#define CO_MSK 576       // G*K
#define CO_TOT 1728
#define MPAD 1792        // 14 * 128
#define KTOT 1152        // CIN * 9
#define NPIX 16384
#define NTOT 32768       // B * NPIX
#define GRP 64

// ---------------- GEMM tiling: 128x128 CTA, 4 warps of 64x64 ----------------
#define MT 128
#define NT 128
#define KC 64
#define NSTAGE 3
#define NCHUNK (KTOT / KC)          // 18
#define LDPh 72                     // padded row length in halves (144 B)
#define TILE_HALVES (128 * LDPh)
#define STAGE_HALVES (2 * TILE_HALVES)
#define SMEM_BYTES (NSTAGE * STAGE_HALVES * 2)   // 110592 B

// im2col staging
#define I2C_PIX 16
#define I2C_PAD 1192

// ---------------- scratch (__device__ globals; no allocs) ----------------
__device__ __half g_offset[(size_t)2 * CO_OFF * NPIX];   // fp16 intermediates
__device__ __half g_mask  [(size_t)2 * CO_MSK * NPIX];
__device__ __half g_colsh [(size_t)NTOT * KTOT];
__device__ __half g_wTh   [(size_t)MPAD * KTOT];

// ---------------- helpers ----------------
__device__ __forceinline__ uint32_t smem_u32(const void* p) {
    uint32_t a;
    asm("{ .reg .u64 t; cvta.to.shared.u64 t, %1; cvt.u32.u64 %0, t; }" : "=r"(a) : "l"(p));
    return a;
}
__device__ __forceinline__ void cpasync16(uint32_t dst, const void* src) {
    asm volatile("cp.async.cg.shared.global [%0], [%1], 16;" :: "r"(dst), "l"(src));
}
__device__ __forceinline__ void ldmx4(uint32_t* r, uint32_t addr) {
    asm volatile("ldmatrix.sync.aligned.m8n8.x4.shared.b16 {%0,%1,%2,%3}, [%4];"
                 : "=r"(r[0]), "=r"(r[1]), "=r"(r[2]), "=r"(r[3]) : "r"(addr));
}
__device__ __forceinline__ void mma_f16_16x8x16(float* d, const uint32_t* a, const uint32_t* b) {
    asm volatile(
        "mma.sync.aligned.m16n8k16.row.col.f32.f16.f16.f32 "
        "{%0,%1,%2,%3}, {%4,%5,%6,%7}, {%8,%9}, {%0,%1,%2,%3};"
        : "+f"(d[0]), "+f"(d[1]), "+f"(d[2]), "+f"(d[3])
        : "r"(a[0]), "r"(a[1]), "r"(a[2]), "r"(a[3]), "r"(b[0]), "r"(b[1]));
}

// ---------------- stage weights into padded fp16 matrix ----------------
__global__ __launch_bounds__(256) void wstage_kernel(const float* __restrict__ w_off,
                                                     const float* __restrict__ w_msk) {
    size_t idx = (size_t)blockIdx.x * 256 + threadIdx.x;
    if (idx >= (size_t)MPAD * KTOT) return;
    int row = (int)(idx / KTOT);
    int k   = (int)(idx % KTOT);
    float v = 0.f;
    if (row < CO_OFF)      v = w_off[(size_t)row * KTOT + k];
    else if (row < CO_TOT) v = w_msk[(size_t)(row - CO_OFF) * KTOT + k];
    g_wTh[idx] = __float2half_rn(v);
}

// ---------------- im2col: smem-staged, coalesced 16B output ----------------
__global__ __launch_bounds__(256) void im2col_kernel(const float* __restrict__ x) {
    __shared__ __half buf[I2C_PIX * I2C_PAD];

    const int p0 = blockIdx.x * I2C_PIX;
    const int ho = blockIdx.y;
    const int b  = blockIdx.z;
    const int tid = threadIdx.x;
    const int px   = tid & 15;
    const int csub = tid >> 4;

    const int wo  = p0 + px;
    const int hi0 = 2 * ho - 1;
    const int wi0 = 2 * wo - 1;

    for (int cb = 0; cb < CIN; cb += 16) {
        const int cin = cb + csub;
        const float* xc = x + ((size_t)(b * CIN + cin) << 16);
        __half* dst = buf + px * I2C_PAD + cin * 9;
#pragma unroll
        for (int ki = 0; ki < 3; ki++) {
            const int hi = hi0 + ki;
            const bool hv = (unsigned)hi < HIN;
#pragma unroll
            for (int kj = 0; kj < 3; kj++) {
                const int wi = wi0 + kj;
                float v = 0.f;
                if (hv && (unsigned)wi < WIN) v = __ldg(xc + (hi << 8) + wi);
                dst[ki * 3 + kj] = __float2half_rn(v);
            }
        }
    }
    __syncthreads();

    int4* gdst = (int4*)(g_colsh + ((size_t)(b * NPIX + ho * WOUT + p0)) * KTOT);
    const int NG = I2C_PIX * (KTOT / 8);
    for (int i = tid; i < NG; i += 256) {
        const int p = i / (KTOT / 8);
        const int g = i - p * (KTOT / 8);
        gdst[(size_t)p * (KTOT / 8) + g] = ((const int4*)(buf + p * I2C_PAD))[g];
    }
}

// ---------------- fp16 mma.sync GEMM: 4 warps, 64x64 warp tile ----------------
__global__ __launch_bounds__(128, 2) void gemm_kernel(const float* __restrict__ b_off,
                                                      const float* __restrict__ b_msk) {
    extern __shared__ __half smem[];
    const int tid = threadIdx.x, wid = tid >> 5, lane = tid & 31;
    const int gid = lane >> 2;
    const int tig = lane & 3;
    const int warp_m = wid & 1;        // 0..1 (64 rows)
    const int warp_n = wid >> 1;       // 0..1 (64 cols)
    const int m0 = blockIdx.x * MT;
    const int n0 = blockIdx.y * NT;

    const char* abase = (const char*)(g_wTh   + (size_t)m0 * KTOT);
    const char* bbase = (const char*)(g_colsh + (size_t)n0 * KTOT);

#define FILL(j)                                                                      \
    do {                                                                             \
        __half* st = smem + ((j) % NSTAGE) * STAGE_HALVES;                           \
        uint32_t sa  = smem_u32(st);                                                 \
        uint32_t sbp = smem_u32(st + TILE_HALVES);                                   \
        const char* asrc = abase + (size_t)(j) * (KC * 2);                           \
        const char* bsrc = bbase + (size_t)(j) * (KC * 2);                           \
        for (int g = tid; g < 1024; g += 128) {                                      \
            int r = g >> 3, c = g & 7;                                               \
            cpasync16(sa  + (r * LDPh + c * 8) * 2, asrc + (size_t)r * (KTOT * 2) + c * 16); \
            cpasync16(sbp + (r * LDPh + c * 8) * 2, bsrc + (size_t)r * (KTOT * 2) + c * 16); \
        }                                                                            \
    } while (0)

    float d[4][8][4];
#pragma unroll
    for (int i = 0; i < 4; i++)
#pragma unroll
        for (int j = 0; j < 8; j++)
#pragma unroll
            for (int c = 0; c < 4; c++) d[i][j][c] = 0.f;

    const int lrow = lane & 15;
    const int lkof = (lane >> 4) << 3;
    const int bnrow = lane & 7;
    const int bkof  = ((lane >> 3) & 1) << 3;
    const int bblk  = lane >> 4;

    FILL(0); asm volatile("cp.async.commit_group;" ::: "memory");
    FILL(1); asm volatile("cp.async.commit_group;" ::: "memory");

    for (int i = 0; i < NCHUNK; i++) {
        asm volatile("cp.async.wait_group 1;" ::: "memory");
        __syncthreads();

        if (i + 2 < NCHUNK) { FILL(i + 2); }
        asm volatile("cp.async.commit_group;" ::: "memory");

        const __half* As = smem + (i % NSTAGE) * STAGE_HALVES;
        const __half* Bs = As + TILE_HALVES;
        const uint32_t aw = smem_u32(As + (warp_m * 64) * LDPh);
        const uint32_t bw = smem_u32(Bs + (warp_n * 64) * LDPh);

#pragma unroll
        for (int kk = 0; kk < KC; kk += 16) {
            uint32_t a[4][4], b4[4][4];
#pragma unroll
            for (int mt = 0; mt < 4; mt++) {
                uint32_t addr = aw + ((mt * 16 + lrow) * LDPh + kk + lkof) * 2;
                ldmx4(a[mt], addr);
            }
#pragma unroll
            for (int nb = 0; nb < 4; nb++) {
                uint32_t addr = bw + (((nb * 2 + bblk) * 8 + bnrow) * LDPh + kk + bkof) * 2;
                ldmx4(b4[nb], addr);
            }
#pragma unroll
            for (int mt = 0; mt < 4; mt++) {
#pragma unroll
                for (int nb = 0; nb < 4; nb++) {
                    mma_f16_16x8x16(d[mt][nb * 2 + 0], a[mt], &b4[nb][0]);
                    mma_f16_16x8x16(d[mt][nb * 2 + 1], a[mt], &b4[nb][2]);
                }
            }
        }
    }

    const int bidx = n0 >> 14;
    const int pix0 = n0 & (NPIX - 1);

#pragma unroll
    for (int mt = 0; mt < 4; mt++) {
        const int row_lo = m0 + warp_m * 64 + mt * 16 + gid;
#pragma unroll
        for (int half = 0; half < 2; half++) {
            const int row = row_lo + half * 8;
            if (row >= CO_TOT) continue;
            const bool ism = (row >= CO_OFF);
            float bias;
            __half* dst;
            if (ism) {
                bias = __ldg(b_msk + (row - CO_OFF));
                dst = g_mask + (size_t)(bidx * CO_MSK + row - CO_OFF) * NPIX + pix0;
            } else {
                bias = __ldg(b_off + row);
                dst = g_offset + (size_t)(bidx * CO_OFF + row) * NPIX + pix0;
            }
#pragma unroll
            for (int nt = 0; nt < 8; nt++) {
                const int col = warp_n * 64 + nt * 8 + tig * 2;
                float v0 = d[mt][nt][half * 2 + 0] + bias;
                float v1 = d[mt][nt][half * 2 + 1] + bias;
                if (ism) {
                    v0 = 1.f / (1.f + __expf(-v0));
                    v1 = 1.f / (1.f + __expf(-v1));
                }
                *(__half2*)(dst + col) = __floats2half2_rn(v0, v1);
            }
        }
    }
}

// ---------------- probe: occupies ncu's capture slot so gemm (4th) is profiled --
__global__ void probe_kernel() {}

// ---------------- deformable sampling core (R11 proven) ----------------
__global__ __launch_bounds__(128) void deform_kernel(
    const float* __restrict__ x,
    const float* __restrict__ w_deform,
    float* __restrict__ out)
{
    __shared__ float wsh[36];
    const int b = blockIdx.z;
    const int g = blockIdx.y;
    const int pix = blockIdx.x * 128 + threadIdx.x;

    if (threadIdx.x < 36)
        wsh[threadIdx.x] = w_deform[g * 36 + threadIdx.x];
    __syncthreads();

    const int ho = pix >> 7;
    const int wo = pix & 127;

    const __half* offp = g_offset + ((size_t)(b * GRP + g) * 18) * NPIX + pix;
    const __half* mp   = g_mask   + ((size_t)(b * GRP + g) * 9)  * NPIX + pix;
    const float* xc0  = x + (size_t)(b * CIN + g * 2) * (HIN * WIN);
    const float* xc1  = xc0 + HIN * WIN;

    float acc0 = 0.f, acc1 = 0.f;

#pragma unroll
    for (int k = 0; k < 9; k++) {
        const float dy = __half2float(offp[(2 * k)     * NPIX]);
        const float dx = __half2float(offp[(2 * k + 1) * NPIX]);
        const float m  = __half2float(mp[k * NPIX]);

        const float py = dy + (float)(2 * ho - 1 + k / 3);
        const float px = dx + (float)(2 * wo - 1 + k % 3);
        const float yf = floorf(py);
        const float xf = floorf(px);
        const int y0 = (int)yf;
        const int x0 = (int)xf;
        const float wy = py - yf;
        const float wx = px - xf;

        float v0 = 0.f, v1 = 0.f;
#pragma unroll
        for (int c2 = 0; c2 < 4; c2++) {
            const int yy = y0 + (c2 >> 1);
            const int xx = x0 + (c2 & 1);
            const float wt = ((c2 >> 1) ? wy : (1.f - wy)) *
                             ((c2 & 1)  ? wx : (1.f - wx));
            if (yy >= 0 && yy < HIN && xx >= 0 && xx < WIN) {
                const int idx = yy * WIN + xx;
                v0 += wt * __ldg(xc0 + idx);
                v1 += wt * __ldg(xc1 + idx);
            }
        }
        v0 *= m;
        v1 *= m;
        acc0 += wsh[k]      * v0 + wsh[9 + k]  * v1;
        acc1 += wsh[18 + k] * v0 + wsh[27 + k] * v1;
    }

    out[((size_t)(b * CIN + g * 2))     * NPIX + pix] = acc0;
    out[((size_t)(b * CIN + g * 2) + 1) * NPIX + pix] = acc1;
}

// ---------------- launch ----------------
extern "C" void kernel_launch(void* const* d_in, const int* in_sizes, int n_in,
                              void* d_out, int out_size)
{
    const float* x        = (const float*)d_in[0];
    const float* w_offset = (const float*)d_in[1];
    const float* b_offset = (const float*)d_in[2];
    const float* w_mask   = (const float*)d_in[3];
    const float* b_mask   = (const float*)d_in[4];
    const float* w_deform = (const float*)d_in[5];
    float* out = (float*)d_out;

    wstage_kernel<<<(MPAD * KTOT + 255) / 256, 256>>>(w_offset, w_mask);
    im2col_kernel<<<dim3(WOUT / I2C_PIX, HOUT, 2), 256>>>(x);

    probe_kernel<<<1, 32>>>();   // position 3: puts gemm_kernel in ncu's slot 4

    cudaFuncSetAttribute(gemm_kernel, cudaFuncAttributeMaxDynamicSharedMemorySize,
                         SMEM_BYTES);
    gemm_kernel<<<dim3(MPAD / MT, NTOT / NT), 128, SMEM_BYTES>>>(b_offset, b_mask);

    deform_kernel<<<dim3(NPIX / 128, GRP, 2), 128>>>(x, w_deform, out);
}

// round 16
// speedup vs baseline: 1.0482x; 1.0482x over previous
#include <cuda_runtime.h>
#include <cuda_fp16.h>
#include <cstdint>
#include <math.h>

// ---------------- problem constants ----------------
#define HIN 256
#define WIN 256
#define HOUT 128
#define WOUT 128
#define CIN 128
#define CO_OFF 1152      // G*2*K
#define CO_MSK 576       // G*K
#define CO_TOT 1728
#define MPAD 1792        // 14 * 128
#define KTOT 1152        // CIN * 9
#define NPIX 16384
#define NTOT 32768       // B * NPIX
#define GRP 64

// ---------------- GEMM tiling (R7/R11 proven config) ----------------
#define MT 128
#define NT 128
#define KC 64
#define NSTAGE 3
#define NCHUNK (KTOT / KC)          // 18
#define LDPh 72                     // padded row length in halves (144 B)
#define TILE_HALVES (128 * LDPh)
#define STAGE_HALVES (2 * TILE_HALVES)
#define SMEM_BYTES (NSTAGE * STAGE_HALVES * 2)   // 110592 B

// im2col staging
#define I2C_PIX 16
#define I2C_PAD 1192

// ---------------- scratch (__device__ globals; no allocs) ----------------
__device__ __half g_offset[(size_t)2 * CO_OFF * NPIX];   // fp16 intermediates
__device__ __half g_mask  [(size_t)2 * CO_MSK * NPIX];
__device__ __half g_colsh [(size_t)NTOT * KTOT];
__device__ __half g_wTh   [(size_t)MPAD * KTOT];

// ---------------- helpers ----------------
__device__ __forceinline__ uint32_t smem_u32(const void* p) {
    uint32_t a;
    asm("{ .reg .u64 t; cvta.to.shared.u64 t, %1; cvt.u32.u64 %0, t; }" : "=r"(a) : "l"(p));
    return a;
}
__device__ __forceinline__ void cpasync16(uint32_t dst, const void* src) {
    asm volatile("cp.async.cg.shared.global [%0], [%1], 16;" :: "r"(dst), "l"(src));
}
__device__ __forceinline__ void ldmx4(uint32_t* r, uint32_t addr) {
    asm volatile("ldmatrix.sync.aligned.m8n8.x4.shared.b16 {%0,%1,%2,%3}, [%4];"
                 : "=r"(r[0]), "=r"(r[1]), "=r"(r[2]), "=r"(r[3]) : "r"(addr));
}
__device__ __forceinline__ void mma_f16_16x8x16(float* d, const uint32_t* a, const uint32_t* b) {
    asm volatile(
        "mma.sync.aligned.m16n8k16.row.col.f32.f16.f16.f32 "
        "{%0,%1,%2,%3}, {%4,%5,%6,%7}, {%8,%9}, {%0,%1,%2,%3};"
        : "+f"(d[0]), "+f"(d[1]), "+f"(d[2]), "+f"(d[3])
        : "r"(a[0]), "r"(a[1]), "r"(a[2]), "r"(a[3]), "r"(b[0]), "r"(b[1]));
}

// ---------------- stage weights into padded fp16 matrix ----------------
__global__ __launch_bounds__(256) void wstage_kernel(const float* __restrict__ w_off,
                                                     const float* __restrict__ w_msk) {
    size_t idx = (size_t)blockIdx.x * 256 + threadIdx.x;
    if (idx >= (size_t)MPAD * KTOT) return;
    int row = (int)(idx / KTOT);
    int k   = (int)(idx % KTOT);
    float v = 0.f;
    if (row < CO_OFF)      v = w_off[(size_t)row * KTOT + k];
    else if (row < CO_TOT) v = w_msk[(size_t)(row - CO_OFF) * KTOT + k];
    g_wTh[idx] = __float2half_rn(v);
}

// ---------------- im2col: smem-staged, coalesced 16B output ----------------
__global__ __launch_bounds__(256) void im2col_kernel(const float* __restrict__ x) {
    __shared__ __half buf[I2C_PIX * I2C_PAD];

    const int p0 = blockIdx.x * I2C_PIX;
    const int ho = blockIdx.y;
    const int b  = blockIdx.z;
    const int tid = threadIdx.x;
    const int px   = tid & 15;
    const int csub = tid >> 4;

    const int wo  = p0 + px;
    const int hi0 = 2 * ho - 1;
    const int wi0 = 2 * wo - 1;

    for (int cb = 0; cb < CIN; cb += 16) {
        const int cin = cb + csub;
        const float* xc = x + ((size_t)(b * CIN + cin) << 16);
        __half* dst = buf + px * I2C_PAD + cin * 9;
#pragma unroll
        for (int ki = 0; ki < 3; ki++) {
            const int hi = hi0 + ki;
            const bool hv = (unsigned)hi < HIN;
#pragma unroll
            for (int kj = 0; kj < 3; kj++) {
                const int wi = wi0 + kj;
                float v = 0.f;
                if (hv && (unsigned)wi < WIN) v = __ldg(xc + (hi << 8) + wi);
                dst[ki * 3 + kj] = __float2half_rn(v);
            }
        }
    }
    __syncthreads();

    int4* gdst = (int4*)(g_colsh + ((size_t)(b * NPIX + ho * WOUT + p0)) * KTOT);
    const int NG = I2C_PIX * (KTOT / 8);
    for (int i = tid; i < NG; i += 256) {
        const int p = i / (KTOT / 8);
        const int g = i - p * (KTOT / 8);
        gdst[(size_t)p * (KTOT / 8) + g] = ((const int4*)(buf + p * I2C_PAD))[g];
    }
}

// ---------------- fp16 mma.sync GEMM (ldmatrix) + fused epilogue ----------------
__global__ __launch_bounds__(256, 2) void gemm_kernel(const float* __restrict__ b_off,
                                                      const float* __restrict__ b_msk) {
    extern __shared__ __half smem[];
    const int tid = threadIdx.x, wid = tid >> 5, lane = tid & 31;
    const int gid = lane >> 2;
    const int tig = lane & 3;
    const int warp_m = wid & 1;
    const int warp_n = wid >> 1;
    const int m0 = blockIdx.x * MT;
    const int n0 = blockIdx.y * NT;

    const char* abase = (const char*)(g_wTh   + (size_t)m0 * KTOT);
    const char* bbase = (const char*)(g_colsh + (size_t)n0 * KTOT);

#define FILL(j)                                                                      \
    do {                                                                             \
        __half* st = smem + ((j) % NSTAGE) * STAGE_HALVES;                           \
        uint32_t sa  = smem_u32(st);                                                 \
        uint32_t sbp = smem_u32(st + TILE_HALVES);                                   \
        const char* asrc = abase + (size_t)(j) * (KC * 2);                           \
        const char* bsrc = bbase + (size_t)(j) * (KC * 2);                           \
        for (int g = tid; g < 1024; g += 256) {                                      \
            int r = g >> 3, c = g & 7;                                               \
            cpasync16(sa  + (r * LDPh + c * 8) * 2, asrc + (size_t)r * (KTOT * 2) + c * 16); \
            cpasync16(sbp + (r * LDPh + c * 8) * 2, bsrc + (size_t)r * (KTOT * 2) + c * 16); \
        }                                                                            \
    } while (0)

    float d[4][4][4];
#pragma unroll
    for (int i = 0; i < 4; i++)
#pragma unroll
        for (int j = 0; j < 4; j++)
#pragma unroll
            for (int c = 0; c < 4; c++) d[i][j][c] = 0.f;

    const int lrow = lane & 15;
    const int lkof = (lane >> 4) << 3;
    const int bnrow = lane & 7;
    const int bkof  = ((lane >> 3) & 1) << 3;
    const int bblk  = lane >> 4;

    FILL(0); asm volatile("cp.async.commit_group;" ::: "memory");
    FILL(1); asm volatile("cp.async.commit_group;" ::: "memory");

    for (int i = 0; i < NCHUNK; i++) {
        asm volatile("cp.async.wait_group 1;" ::: "memory");
        __syncthreads();

        if (i + 2 < NCHUNK) { FILL(i + 2); }
        asm volatile("cp.async.commit_group;" ::: "memory");

        const __half* As = smem + (i % NSTAGE) * STAGE_HALVES;
        const __half* Bs = As + TILE_HALVES;
        const uint32_t aw = smem_u32(As + (warp_m * 64) * LDPh);
        const uint32_t bw = smem_u32(Bs + (warp_n * 32) * LDPh);

#pragma unroll
        for (int kk = 0; kk < KC; kk += 16) {
            uint32_t a[4][4], b2[2][4];
#pragma unroll
            for (int mt = 0; mt < 4; mt++) {
                uint32_t addr = aw + ((mt * 16 + lrow) * LDPh + kk + lkof) * 2;
                ldmx4(a[mt], addr);
            }
#pragma unroll
            for (int nb = 0; nb < 2; nb++) {
                uint32_t addr = bw + (((nb * 2 + bblk) * 8 + bnrow) * LDPh + kk + bkof) * 2;
                ldmx4(b2[nb], addr);
            }
#pragma unroll
            for (int mt = 0; mt < 4; mt++) {
#pragma unroll
                for (int nb = 0; nb < 2; nb++) {
                    mma_f16_16x8x16(d[mt][nb * 2 + 0], a[mt], &b2[nb][0]);
                    mma_f16_16x8x16(d[mt][nb * 2 + 1], a[mt], &b2[nb][2]);
                }
            }
        }
    }

    const int bidx = n0 >> 14;
    const int pix0 = n0 & (NPIX - 1);

#pragma unroll
    for (int mt = 0; mt < 4; mt++) {
        const int row_lo = m0 + warp_m * 64 + mt * 16 + gid;
#pragma unroll
        for (int half = 0; half < 2; half++) {
            const int row = row_lo + half * 8;
            if (row >= CO_TOT) continue;
            const bool ism = (row >= CO_OFF);
            float bias;
            __half* dst;
            if (ism) {
                bias = __ldg(b_msk + (row - CO_OFF));
                dst = g_mask + (size_t)(bidx * CO_MSK + row - CO_OFF) * NPIX + pix0;
            } else {
                bias = __ldg(b_off + row);
                dst = g_offset + (size_t)(bidx * CO_OFF + row) * NPIX + pix0;
            }
#pragma unroll
            for (int nt = 0; nt < 4; nt++) {
                const int col = warp_n * 32 + nt * 8 + tig * 2;
                float v0 = d[mt][nt][half * 2 + 0] + bias;
                float v1 = d[mt][nt][half * 2 + 1] + bias;
                if (ism) {
                    v0 = 1.f / (1.f + __expf(-v0));
                    v1 = 1.f / (1.f + __expf(-v1));
                }
                *(__half2*)(dst + col) = __floats2half2_rn(v0, v1);
            }
        }
    }
}

// ---------------- deformable sampling core (R11 proven) ----------------
__global__ __launch_bounds__(128) void deform_kernel(
    const float* __restrict__ x,
    const float* __restrict__ w_deform,
    float* __restrict__ out)
{
    __shared__ float wsh[36];
    const int b = blockIdx.z;
    const int g = blockIdx.y;
    const int pix = blockIdx.x * 128 + threadIdx.x;

    if (threadIdx.x < 36)
        wsh[threadIdx.x] = w_deform[g * 36 + threadIdx.x];
    __syncthreads();

    const int ho = pix >> 7;
    const int wo = pix & 127;

    const __half* offp = g_offset + ((size_t)(b * GRP + g) * 18) * NPIX + pix;
    const __half* mp   = g_mask   + ((size_t)(b * GRP + g) * 9)  * NPIX + pix;
    const float* xc0  = x + (size_t)(b * CIN + g * 2) * (HIN * WIN);
    const float* xc1  = xc0 + HIN * WIN;

    float acc0 = 0.f, acc1 = 0.f;

#pragma unroll
    for (int k = 0; k < 9; k++) {
        const float dy = __half2float(offp[(2 * k)     * NPIX]);
        const float dx = __half2float(offp[(2 * k + 1) * NPIX]);
        const float m  = __half2float(mp[k * NPIX]);

        const float py = dy + (float)(2 * ho - 1 + k / 3);
        const float px = dx + (float)(2 * wo - 1 + k % 3);
        const float yf = floorf(py);
        const float xf = floorf(px);
        const int y0 = (int)yf;
        const int x0 = (int)xf;
        const float wy = py - yf;
        const float wx = px - xf;

        float v0 = 0.f, v1 = 0.f;
#pragma unroll
        for (int c2 = 0; c2 < 4; c2++) {
            const int yy = y0 + (c2 >> 1);
            const int xx = x0 + (c2 & 1);
            const float wt = ((c2 >> 1) ? wy : (1.f - wy)) *
                             ((c2 & 1)  ? wx : (1.f - wx));
            if (yy >= 0 && yy < HIN && xx >= 0 && xx < WIN) {
                const int idx = yy * WIN + xx;
                v0 += wt * __ldg(xc0 + idx);
                v1 += wt * __ldg(xc1 + idx);
            }
        }
        v0 *= m;
        v1 *= m;
        acc0 += wsh[k]      * v0 + wsh[9 + k]  * v1;
        acc1 += wsh[18 + k] * v0 + wsh[27 + k] * v1;
    }

    out[((size_t)(b * CIN + g * 2))     * NPIX + pix] = acc0;
    out[((size_t)(b * CIN + g * 2) + 1) * NPIX + pix] = acc1;
}

// ---------------- launch ----------------
extern "C" void kernel_launch(void* const* d_in, const int* in_sizes, int n_in,
                              void* d_out, int out_size)
{
    const float* x        = (const float*)d_in[0];
    const float* w_offset = (const float*)d_in[1];
    const float* b_offset = (const float*)d_in[2];
    const float* w_mask   = (const float*)d_in[3];
    const float* b_mask   = (const float*)d_in[4];
    const float* w_deform = (const float*)d_in[5];
    float* out = (float*)d_out;

    wstage_kernel<<<(MPAD * KTOT + 255) / 256, 256>>>(w_offset, w_mask);
    im2col_kernel<<<dim3(WOUT / I2C_PIX, HOUT, 2), 256>>>(x);

    cudaFuncSetAttribute(gemm_kernel, cudaFuncAttributeMaxDynamicSharedMemorySize,
                         SMEM_BYTES);
    gemm_kernel<<<dim3(MPAD / MT, NTOT / NT), 256, SMEM_BYTES>>>(b_offset, b_mask);

    deform_kernel<<<dim3(NPIX / 128, GRP, 2), 128>>>(x, w_deform, out);
}